// round 1
// baseline (speedup 1.0000x reference)
#include <cuda_runtime.h>
#include <cuda_bf16.h>

// CoPEWithFIRE: B=1, H=12, S=768, W=32
// out[h,i,j] = b_out[h] + sum_w W_out[h,w] * relu(dist[h,i,j]*W_in[w,0] + b_in[w])
// dist = log(|c|*pos + 1) / (log(|c|*min(pos_total, |Lm*initL|) + 1) + 1e-6)
// pos[h,i,j] = suffix-sum over j of sigmoid(logits[h,i,j])

#define CPF_S 768
#define CPF_H 12
#define CPF_W 32
#define CPF_NWARPS (CPF_S / 32)   // 24

__global__ __launch_bounds__(CPF_S, 2)
void cope_fire_kernel(const float* __restrict__ logits,
                      const float* __restrict__ W_in,
                      const float* __restrict__ b_in,
                      const float* __restrict__ W_out,
                      const float* __restrict__ b_out,
                      const float* __restrict__ c_ptr,
                      const float* __restrict__ lm_ptr,
                      const float* __restrict__ il_ptr,
                      float* __restrict__ out)
{
    __shared__ float s_w1[CPF_W];
    __shared__ float s_bi[CPF_W];
    __shared__ float s_wo[CPF_W];
    __shared__ float s_wsuf[CPF_NWARPS + 1];  // suffix sums of warp totals
    __shared__ float s_wsum[CPF_NWARPS];
    __shared__ float s_bout;

    const int tid  = threadIdx.x;
    const int lane = tid & 31;
    const int wid  = tid >> 5;

    const int row = blockIdx.x;           // row = h*S + i
    const int h   = row / CPF_S;
    const long long base = (long long)row * CPF_S;

    // Stage weights into shared (broadcast reads later, N=1 no conflicts)
    if (tid < CPF_W) {
        s_w1[tid] = W_in[tid];            // W_in[:,0]
        s_bi[tid] = b_in[tid];
        s_wo[tid] = W_out[h * CPF_W + tid];
    }
    if (tid == 0) s_bout = b_out[h];

    // 1) gate = sigmoid(logit)
    float x = logits[base + tid];
    float g = 1.0f / (1.0f + __expf(-x));

    // 2) suffix-sum within warp: v = sum_{k>=lane} g_k
    float v = g;
    #pragma unroll
    for (int off = 1; off < 32; off <<= 1) {
        float t = __shfl_down_sync(0xFFFFFFFFu, v, off);
        if (lane + off < 32) v += t;
    }
    if (lane == 0) s_wsum[wid] = v;       // warp total
    __syncthreads();

    // 3) warp 0: suffix-scan of the 24 warp totals
    if (wid == 0) {
        float wv = (lane < CPF_NWARPS) ? s_wsum[lane] : 0.0f;
        #pragma unroll
        for (int off = 1; off < 32; off <<= 1) {
            float t = __shfl_down_sync(0xFFFFFFFFu, wv, off);
            if (lane + off < 32) wv += t;
        }
        if (lane < CPF_NWARPS) s_wsuf[lane] = wv;  // sum of warp totals [lane..23]
        if (lane == 0) s_wsuf[CPF_NWARPS] = 0.0f;
    }
    __syncthreads();

    // pos[j] = within-warp suffix + totals of later warps
    float pos   = v + s_wsuf[wid + 1];
    float total = s_wsuf[0];              // pos at j=0 (max_pos)

    // 4) dist = log(|c|*pos+1) / (log(|c|*min(total, thr)+1) + EPS)
    const float cabs = fabsf(*c_ptr);
    const float thr  = fabsf((*lm_ptr) * (*il_ptr));
    const float denom = __logf(cabs * fminf(total, thr) + 1.0f) + 1e-6f;
    const float inv_denom = 1.0f / denom;
    const float dist = __logf(cabs * pos + 1.0f) * inv_denom;

    // 5) 32-wide ReLU MLP + output dot
    float acc = s_bout;
    #pragma unroll
    for (int w = 0; w < CPF_W; ++w) {
        float hdn = fmaxf(fmaf(dist, s_w1[w], s_bi[w]), 0.0f);
        acc = fmaf(hdn, s_wo[w], acc);
    }

    out[base + tid] = acc;
}

extern "C" void kernel_launch(void* const* d_in, const int* in_sizes, int n_in,
                              void* d_out, int out_size)
{
    const float* logits = (const float*)d_in[0];  // (1,12,768,768)
    const float* W_in   = (const float*)d_in[1];  // (32,1)
    const float* b_in   = (const float*)d_in[2];  // (32,)
    const float* W_out  = (const float*)d_in[3];  // (12,32)
    const float* b_out  = (const float*)d_in[4];  // (12,)
    const float* c      = (const float*)d_in[5];
    const float* lmul   = (const float*)d_in[6];
    const float* initL  = (const float*)d_in[7];
    float* out = (float*)d_out;

    dim3 grid(CPF_H * CPF_S);   // 9216 rows
    dim3 block(CPF_S);          // 768 threads, one per j
    cope_fire_kernel<<<grid, block>>>(logits, W_in, b_in, W_out, b_out,
                                      c, lmul, initL, out);
}

// round 2
// speedup vs baseline: 1.9846x; 1.9846x over previous
#include <cuda_runtime.h>
#include <cuda_bf16.h>
#include <math_constants.h>

// CoPEWithFIRE: B=1, H=12, S=768, W=32
// out[h,i,j] = f_h(dist[h,i,j]) where f_h is piecewise-linear (32 ReLU units).
// dist = log(|c|*pos + 1) / (log(|c|*min(pos_row_total, |Lm*initL|) + 1) + 1e-6)
// pos[h,i,j] = suffix-sum over j of sigmoid(logits[h,i,j])

#define CPF_S 768
#define CPF_H 12
#define CPF_W 32
#define CPF_CHUNKS 6          // 6 chunks of 128 elems (32 lanes x 4) per row

// Per-head PWL tables: 33 segments (slope, intercept), 32 sorted breakpoints.
__device__ float g_pwl_slope[CPF_H][33];
__device__ float g_pwl_icept[CPF_H][33];
__device__ float g_pwl_bp[CPF_H][32];

// ---------------------------------------------------------------------------
// Setup: build exact PWL representation of the per-head MLP. Runs once per
// launch (1 block, 12 threads, trivial cost).
// ---------------------------------------------------------------------------
__global__ void cope_fire_setup(const float* __restrict__ W_in,
                                const float* __restrict__ b_in,
                                const float* __restrict__ W_out,
                                const float* __restrict__ b_out)
{
    int h = threadIdx.x;
    if (h >= CPF_H) return;

    float w1v[CPF_W], biv[CPF_W], wov[CPF_W];
    float bp[CPF_W];
    int n = 0;
    float base_ic = b_out[h];

    for (int w = 0; w < CPF_W; ++w) {
        w1v[w] = W_in[w];           // W_in[:,0]
        biv[w] = b_in[w];
        wov[w] = W_out[h * CPF_W + w];
        if (w1v[w] != 0.0f) {
            bp[n++] = -biv[w] / w1v[w];
        } else {
            base_ic += wov[w] * fmaxf(biv[w], 0.0f);  // constant unit
        }
    }

    // insertion sort breakpoints
    for (int a = 1; a < n; ++a) {
        float key = bp[a];
        int b = a - 1;
        while (b >= 0 && bp[b] > key) { bp[b + 1] = bp[b]; --b; }
        bp[b + 1] = key;
    }

    for (int s = 0; s <= CPF_W; ++s) {
        float mid;
        if (n == 0)          mid = 0.0f;
        else if (s == 0)     mid = bp[0] - 1.0f;
        else if (s >= n)     mid = bp[n - 1] + 1.0f;
        else                 mid = 0.5f * (bp[s - 1] + bp[s]);

        float sl = 0.0f, ic = base_ic;
        for (int w = 0; w < CPF_W; ++w) {
            if (w1v[w] != 0.0f && (w1v[w] * mid + biv[w]) > 0.0f) {
                sl += wov[w] * w1v[w];
                ic += wov[w] * biv[w];
            }
        }
        g_pwl_slope[h][s] = sl;
        g_pwl_icept[h][s] = ic;
    }
    for (int s = 0; s < CPF_W; ++s)
        g_pwl_bp[h][s] = (s < n) ? bp[s] : 3.0e38f;   // pad: never counted
}

// ---------------------------------------------------------------------------
// Main kernel: one WARP per row. 256 threads/block = 8 rows/block.
// Lane handles elements j = 128*k + 4*lane + m  (k=0..5, m=0..3): float4 I/O.
// Suffix sum = in-thread 4-chain + per-chunk warp shuffle scan. No barriers
// in the hot path.
// ---------------------------------------------------------------------------
__global__ __launch_bounds__(256)
void cope_fire_main(const float* __restrict__ logits,
                    const float* __restrict__ c_ptr,
                    const float* __restrict__ lm_ptr,
                    const float* __restrict__ il_ptr,
                    float* __restrict__ out)
{
    __shared__ float s_bp[CPF_W];
    __shared__ float s_sl[CPF_W + 1];
    __shared__ float s_ic[CPF_W + 1];

    const int tid  = threadIdx.x;
    const int lane = tid & 31;
    const int wid  = tid >> 5;

    const int row = blockIdx.x * 8 + wid;     // 8 rows per block; 768%8==0 so
    const int h   = row / CPF_S;              // all rows in a block share h

    if (tid <= CPF_W) {
        s_sl[tid] = g_pwl_slope[h][tid];
        s_ic[tid] = g_pwl_icept[h][tid];
        if (tid < CPF_W) s_bp[tid] = g_pwl_bp[h][tid];
    }
    __syncthreads();

    const long long base = (long long)row * CPF_S;
    const float4* inp = (const float4*)(logits + base);
    float4*       op  = (float4*)(out + base);

    // --- load + sigmoid ---
    float g[CPF_CHUNKS][4];
    #pragma unroll
    for (int k = 0; k < CPF_CHUNKS; ++k) {
        float4 v = inp[k * 32 + lane];
        g[k][0] = 1.0f / (1.0f + __expf(-v.x));
        g[k][1] = 1.0f / (1.0f + __expf(-v.y));
        g[k][2] = 1.0f / (1.0f + __expf(-v.z));
        g[k][3] = 1.0f / (1.0f + __expf(-v.w));
    }

    // --- in-thread suffix within each 4-chunk (overwrite g with suffixes) ---
    float csum[CPF_CHUNKS];
    #pragma unroll
    for (int k = 0; k < CPF_CHUNKS; ++k) {
        g[k][2] += g[k][3];
        g[k][1] += g[k][2];
        g[k][0] += g[k][1];
        csum[k] = g[k][0];
    }

    // --- per-chunk warp suffix scan of thread sums ---
    float after[CPF_CHUNKS];   // sum over lanes > me within chunk k
    float Ctot[CPF_CHUNKS];    // warp total of chunk k
    #pragma unroll
    for (int k = 0; k < CPF_CHUNKS; ++k) {
        float v = csum[k];
        #pragma unroll
        for (int off = 1; off < 32; off <<= 1) {
            float t = __shfl_down_sync(0xFFFFFFFFu, v, off);
            if (lane + off < 32) v += t;
        }
        after[k] = v - csum[k];
        Ctot[k]  = __shfl_sync(0xFFFFFFFFu, v, 0);
    }

    // suffix of chunk totals: A[k] = sum_{k'>k} Ctot[k']
    float A[CPF_CHUNKS];
    A[CPF_CHUNKS - 1] = 0.0f;
    #pragma unroll
    for (int k = CPF_CHUNKS - 2; k >= 0; --k) A[k] = A[k + 1] + Ctot[k + 1];
    const float row_total = Ctot[0] + A[0];   // pos at j=0 (max_pos)

    // --- dist scale ---
    const float cabs = fabsf(*c_ptr);
    const float thr  = fabsf((*lm_ptr) * (*il_ptr));
    const float denom = __logf(fmaf(cabs, fminf(row_total, thr), 1.0f)) + 1e-6f;
    const float inv_denom = 1.0f / denom;

    // --- evaluate: dist -> PWL segment -> fma -> store ---
    #pragma unroll
    for (int k = 0; k < CPF_CHUNKS; ++k) {
        const float add = after[k] + A[k];
        float4 r;
        float* rp = &r.x;
        #pragma unroll
        for (int m = 0; m < 4; ++m) {
            float pos = g[k][m] + add;
            float d = __logf(fmaf(cabs, pos, 1.0f)) * inv_denom;
            // branchless lower-bound: seg = #breakpoints <= d, in [0,32]
            int seg = 0;
            #pragma unroll
            for (int st = 16; st >= 1; st >>= 1) {
                int cand = seg + st;
                seg = (d >= s_bp[cand - 1]) ? cand : seg;
            }
            rp[m] = fmaf(d, s_sl[seg], s_ic[seg]);
        }
        op[k * 32 + lane] = r;
    }
}

extern "C" void kernel_launch(void* const* d_in, const int* in_sizes, int n_in,
                              void* d_out, int out_size)
{
    const float* logits = (const float*)d_in[0];  // (1,12,768,768)
    const float* W_in   = (const float*)d_in[1];  // (32,1)
    const float* b_in   = (const float*)d_in[2];  // (32,)
    const float* W_out  = (const float*)d_in[3];  // (12,32)
    const float* b_out  = (const float*)d_in[4];  // (12,)
    const float* c      = (const float*)d_in[5];
    const float* lmul   = (const float*)d_in[6];
    const float* initL  = (const float*)d_in[7];
    float* out = (float*)d_out;

    cope_fire_setup<<<1, CPF_H>>>(W_in, b_in, W_out, b_out);
    cope_fire_main<<<(CPF_H * CPF_S) / 8, 256>>>(logits, c, lmul, initL, out);
}

// round 3
// speedup vs baseline: 3.9450x; 1.9878x over previous
#include <cuda_runtime.h>
#include <cuda_bf16.h>

// CoPEWithFIRE fused single kernel: B=1, H=12, S=768, W=32
// f_h(dist) is piecewise-linear (32 ReLU breakpoints); built warp-parallel
// per block. Search runs in the pos domain (monotone transform of dist) so
// it overlaps the per-element log.

#define CPF_S 768
#define CPF_H 12
#define CPF_W 32
#define CPF_CHUNKS 6
#define CPF_RPB 8      // rows (warps) per block

__global__ __launch_bounds__(256)
void cope_fire_fused(const float* __restrict__ logits,
                     const float* __restrict__ W_in,
                     const float* __restrict__ b_in,
                     const float* __restrict__ W_out,
                     const float* __restrict__ b_out,
                     const float* __restrict__ c_ptr,
                     const float* __restrict__ lm_ptr,
                     const float* __restrict__ il_ptr,
                     float* __restrict__ out)
{
    __shared__ float s_bp[CPF_W];          // sorted breakpoints (dist domain)
    __shared__ float s_sl[CPF_W + 1];      // slopes per segment
    __shared__ float s_ic[CPF_W + 1];      // intercepts per segment
    __shared__ float s_tmp[CPF_W];         // warp-0 scratch
    __shared__ float s_pbp[CPF_RPB][CPF_W];      // per-warp pos-domain bps
    __shared__ float s_sl2[CPF_RPB][CPF_W + 1];  // per-warp slope*inv_denom

    const int tid  = threadIdx.x;
    const int lane = tid & 31;
    const int wid  = tid >> 5;

    const int row = blockIdx.x * CPF_RPB + wid;  // 768 rows/head % 8 == 0:
    const int h   = row / CPF_S;                 // whole block shares h

    const float cabs = fabsf(*c_ptr);

    // ---------------- warp 0: build PWL tables for head h ----------------
    if (wid == 0) {
        const int w = lane;
        float w1 = W_in[w];                  // W_in[:,0]
        float bi = b_in[w];
        float wo = W_out[h * CPF_W + w];
        bool  zero = (w1 == 0.0f);
        float bp  = zero ? 3.0e38f : (-bi / w1);
        float dsl = zero ? 0.0f : wo * fabsf(w1);
        float dic = zero ? 0.0f : ((w1 > 0.0f) ? wo * bi : -wo * bi);
        // base (d -> -inf): units with w1<0 are active; w1==0 contributes const
        float bsl = (!zero && w1 < 0.0f) ? wo * w1 : 0.0f;
        float bic = zero ? wo * fmaxf(bi, 0.0f)
                         : ((w1 < 0.0f) ? wo * bi : 0.0f);
        #pragma unroll
        for (int off = 16; off >= 1; off >>= 1) {
            bsl += __shfl_xor_sync(0xFFFFFFFFu, bsl, off);
            bic += __shfl_xor_sync(0xFFFFFFFFu, bic, off);
        }
        bic += b_out[h];

        // rank-sort the 32 breakpoints (stable tie-break on unit index)
        s_tmp[w] = bp;
        __syncwarp();
        int rank = 0;
        #pragma unroll
        for (int q = 0; q < CPF_W; ++q) {
            float o = s_tmp[q];
            rank += (o < bp || (o == bp && q < w)) ? 1 : 0;
        }
        __syncwarp();
        s_bp[rank]  = bp;
        s_tmp[rank] = dsl;
        __syncwarp();
        float v = s_tmp[lane];               // dsl in sorted order
        #pragma unroll
        for (int off = 1; off < 32; off <<= 1) {
            float t = __shfl_up_sync(0xFFFFFFFFu, v, off);
            if (lane >= off) v += t;
        }
        s_sl[lane + 1] = bsl + v;
        if (lane == 0) s_sl[0] = bsl;
        __syncwarp();
        s_tmp[rank] = dic;
        __syncwarp();
        float u = s_tmp[lane];               // dic in sorted order
        #pragma unroll
        for (int off = 1; off < 32; off <<= 1) {
            float t = __shfl_up_sync(0xFFFFFFFFu, u, off);
            if (lane >= off) u += t;
        }
        s_ic[lane + 1] = bic + u;
        if (lane == 0) s_ic[0] = bic;
    }

    // -------- per-warp row: load + sigmoid + suffix scan (no barriers) ----
    const long long base = (long long)row * CPF_S;
    const float4* inp = (const float4*)(logits + base);
    float4*       op  = (float4*)(out + base);

    float g[CPF_CHUNKS][4];
    #pragma unroll
    for (int k = 0; k < CPF_CHUNKS; ++k) {
        float4 v4 = inp[k * 32 + lane];
        g[k][0] = 1.0f / (1.0f + __expf(-v4.x));
        g[k][1] = 1.0f / (1.0f + __expf(-v4.y));
        g[k][2] = 1.0f / (1.0f + __expf(-v4.z));
        g[k][3] = 1.0f / (1.0f + __expf(-v4.w));
    }

    float csum[CPF_CHUNKS];
    #pragma unroll
    for (int k = 0; k < CPF_CHUNKS; ++k) {
        g[k][2] += g[k][3];
        g[k][1] += g[k][2];
        g[k][0] += g[k][1];
        csum[k] = g[k][0];
    }

    float after[CPF_CHUNKS], Ctot[CPF_CHUNKS];
    #pragma unroll
    for (int k = 0; k < CPF_CHUNKS; ++k) {
        float v = csum[k];
        #pragma unroll
        for (int off = 1; off < 32; off <<= 1) {
            float t = __shfl_down_sync(0xFFFFFFFFu, v, off);
            if (lane + off < 32) v += t;
        }
        after[k] = v - csum[k];
        Ctot[k]  = __shfl_sync(0xFFFFFFFFu, v, 0);
    }

    float A[CPF_CHUNKS];
    A[CPF_CHUNKS - 1] = 0.0f;
    #pragma unroll
    for (int k = CPF_CHUNKS - 2; k >= 0; --k) A[k] = A[k + 1] + Ctot[k + 1];
    const float row_total = Ctot[0] + A[0];

    __syncthreads();   // PWL tables ready

    // ------ per-row: pos-domain breakpoints + denom-folded slopes ---------
    const float thr   = fabsf((*lm_ptr) * (*il_ptr));
    const float denom = __logf(fmaf(cabs, fminf(row_total, thr), 1.0f)) + 1e-6f;
    const float inv_denom = 1.0f / denom;
    const float rcp_c = 1.0f / cabs;

    // lane-parallel: pos_bp = (exp(bp*denom)-1)/|c|  (monotone in bp)
    s_pbp[wid][lane] = (__expf(s_bp[lane] * denom) - 1.0f) * rcp_c;
    s_sl2[wid][lane] = s_sl[lane] * inv_denom;
    if (lane == 0) s_sl2[wid][CPF_W] = s_sl[CPF_W] * inv_denom;
    __syncwarp();

    const float* pbp = s_pbp[wid];
    const float* sl2 = s_sl2[wid];

    // ---------------- eval: log || search, then one fma -------------------
    #pragma unroll
    for (int k = 0; k < CPF_CHUNKS; ++k) {
        const float add = after[k] + A[k];
        float4 r;
        float* rp = &r.x;
        #pragma unroll
        for (int m = 0; m < 4; ++m) {
            float pos = g[k][m] + add;
            float t = __logf(fmaf(cabs, pos, 1.0f));   // MUFU chain
            int seg = 0;                                // LDS chain (parallel)
            #pragma unroll
            for (int st = 16; st >= 1; st >>= 1) {
                int cand = seg + st;
                seg = (pos >= pbp[cand - 1]) ? cand : seg;
            }
            rp[m] = fmaf(t, sl2[seg], s_ic[seg]);
        }
        op[k * 32 + lane] = r;
    }
}

extern "C" void kernel_launch(void* const* d_in, const int* in_sizes, int n_in,
                              void* d_out, int out_size)
{
    const float* logits = (const float*)d_in[0];  // (1,12,768,768)
    const float* W_in   = (const float*)d_in[1];  // (32,1)
    const float* b_in   = (const float*)d_in[2];  // (32,)
    const float* W_out  = (const float*)d_in[3];  // (12,32)
    const float* b_out  = (const float*)d_in[4];  // (12,)
    const float* c      = (const float*)d_in[5];
    const float* lmul   = (const float*)d_in[6];
    const float* initL  = (const float*)d_in[7];
    float* out = (float*)d_out;

    cope_fire_fused<<<(CPF_H * CPF_S) / CPF_RPB, 256>>>(
        logits, W_in, b_in, W_out, b_out, c, lmul, initL, out);
}

// round 4
// speedup vs baseline: 4.3139x; 1.0935x over previous
#include <cuda_runtime.h>
#include <cuda_bf16.h>

// CoPEWithFIRE fused: B=1, H=12, S=768, W=32
// PWL representation of the per-head 32-unit ReLU MLP, built warp-parallel.
// Search in the pos domain (overlaps MUFU log chain); top 2 search levels in
// registers, bottom 3 via LDS; (slope,intercept) packed float2.

#define CPF_S 768
#define CPF_H 12
#define CPF_W 32
#define CPF_CHUNKS 6
#define CPF_RPB 8      // rows (warps) per block

__global__ __launch_bounds__(256, 5)
void cope_fire_fused(const float* __restrict__ logits,
                     const float* __restrict__ W_in,
                     const float* __restrict__ b_in,
                     const float* __restrict__ W_out,
                     const float* __restrict__ b_out,
                     const float* __restrict__ c_ptr,
                     const float* __restrict__ lm_ptr,
                     const float* __restrict__ il_ptr,
                     float* __restrict__ out)
{
    __shared__ float  s_bp[CPF_W];          // sorted breakpoints (dist domain)
    __shared__ float  s_sl[CPF_W + 1];      // slopes per segment
    __shared__ float  s_ic[CPF_W + 1];      // intercepts per segment
    __shared__ float  s_tmp[CPF_W];         // warp-0 scratch
    __shared__ float  s_pbp[CPF_RPB][CPF_W];      // pos-domain bps per warp
    __shared__ float2 s_seg[CPF_RPB][CPF_W + 1];  // (slope*inv_denom, icept)

    const int tid  = threadIdx.x;
    const int lane = tid & 31;
    const int wid  = tid >> 5;

    const int row = blockIdx.x * CPF_RPB + wid;  // block shares one head
    const int h   = row / CPF_S;

    const float cabs = fabsf(*c_ptr);

    // ---------------- warp 0: build PWL tables for head h ----------------
    if (wid == 0) {
        const int w = lane;
        float w1 = W_in[w];
        float bi = b_in[w];
        float wo = W_out[h * CPF_W + w];
        bool  zero = (w1 == 0.0f);
        float bp  = zero ? 3.0e38f : (-bi / w1);
        float dsl = zero ? 0.0f : wo * fabsf(w1);
        float dic = zero ? 0.0f : ((w1 > 0.0f) ? wo * bi : -wo * bi);
        float bsl = (!zero && w1 < 0.0f) ? wo * w1 : 0.0f;
        float bic = zero ? wo * fmaxf(bi, 0.0f)
                         : ((w1 < 0.0f) ? wo * bi : 0.0f);
        #pragma unroll
        for (int off = 16; off >= 1; off >>= 1) {
            bsl += __shfl_xor_sync(0xFFFFFFFFu, bsl, off);
            bic += __shfl_xor_sync(0xFFFFFFFFu, bic, off);
        }
        bic += b_out[h];

        s_tmp[w] = bp;
        __syncwarp();
        int rank = 0;
        #pragma unroll
        for (int q = 0; q < CPF_W; ++q) {
            float o = s_tmp[q];
            rank += (o < bp || (o == bp && q < w)) ? 1 : 0;
        }
        __syncwarp();
        s_bp[rank]  = bp;
        s_tmp[rank] = dsl;
        __syncwarp();
        float v = s_tmp[lane];
        #pragma unroll
        for (int off = 1; off < 32; off <<= 1) {
            float t = __shfl_up_sync(0xFFFFFFFFu, v, off);
            if (lane >= off) v += t;
        }
        s_sl[lane + 1] = bsl + v;
        if (lane == 0) s_sl[0] = bsl;
        __syncwarp();
        s_tmp[rank] = dic;
        __syncwarp();
        float u = s_tmp[lane];
        #pragma unroll
        for (int off = 1; off < 32; off <<= 1) {
            float t = __shfl_up_sync(0xFFFFFFFFu, u, off);
            if (lane >= off) u += t;
        }
        s_ic[lane + 1] = bic + u;
        if (lane == 0) s_ic[0] = bic;
    }

    // -------- per-warp row: load + sigmoid + suffix scan ------------------
    const long long base = (long long)row * CPF_S;
    const float4* inp = (const float4*)(logits + base);
    float4*       op  = (float4*)(out + base);

    float g[CPF_CHUNKS][4];
    #pragma unroll
    for (int k = 0; k < CPF_CHUNKS; ++k) {
        float4 v4 = inp[k * 32 + lane];
        g[k][0] = 1.0f / (1.0f + __expf(-v4.x));
        g[k][1] = 1.0f / (1.0f + __expf(-v4.y));
        g[k][2] = 1.0f / (1.0f + __expf(-v4.z));
        g[k][3] = 1.0f / (1.0f + __expf(-v4.w));
    }

    // in-thread suffix within each chunk
    #pragma unroll
    for (int k = 0; k < CPF_CHUNKS; ++k) {
        g[k][2] += g[k][3];
        g[k][1] += g[k][2];
        g[k][0] += g[k][1];
    }

    // per-chunk warp suffix scan of thread sums; fold offsets into g so that
    // g[k][m] ends up as the final pos value (frees all scan temporaries).
    float Ctot[CPF_CHUNKS], after[CPF_CHUNKS];
    #pragma unroll
    for (int k = 0; k < CPF_CHUNKS; ++k) {
        float cs = g[k][0];
        float v = cs;
        #pragma unroll
        for (int off = 1; off < 32; off <<= 1) {
            float t = __shfl_down_sync(0xFFFFFFFFu, v, off);
            if (lane + off < 32) v += t;
        }
        after[k] = v - cs;
        Ctot[k]  = __shfl_sync(0xFFFFFFFFu, v, 0);
    }
    float acc = 0.0f;                       // sum of chunk totals after k
    #pragma unroll
    for (int k = CPF_CHUNKS - 1; k >= 0; --k) {
        float add = after[k] + acc;
        g[k][0] += add; g[k][1] += add; g[k][2] += add; g[k][3] += add;
        acc += Ctot[k];
    }
    const float row_total = acc;            // pos at j=0

    __syncthreads();   // PWL tables ready

    // ------ per-row: pos-domain breakpoints + denom-folded slopes ---------
    const float thr   = fabsf((*lm_ptr) * (*il_ptr));
    const float denom = __logf(fmaf(cabs, fminf(row_total, thr), 1.0f)) + 1e-6f;
    const float inv_denom = 1.0f / denom;
    const float rcp_c = 1.0f / cabs;

    s_pbp[wid][lane] = (__expf(s_bp[lane] * denom) - 1.0f) * rcp_c;
    s_seg[wid][lane] = make_float2(s_sl[lane] * inv_denom, s_ic[lane]);
    if (lane == 0)
        s_seg[wid][CPF_W] = make_float2(s_sl[CPF_W] * inv_denom, s_ic[CPF_W]);
    __syncwarp();

    const float*  pbp  = s_pbp[wid];
    const float2* segt = s_seg[wid];

    // row-uniform top search levels in registers
    const float r15 = pbp[15];
    const float r7  = pbp[7];
    const float r23 = pbp[23];

    // ---------------- eval: log || search, then one fma -------------------
    #pragma unroll
    for (int k = 0; k < CPF_CHUNKS; ++k) {
        float4 r;
        float* rp = &r.x;
        #pragma unroll
        for (int m = 0; m < 4; ++m) {
            const float pos = g[k][m];
            const float t = __logf(fmaf(cabs, pos, 1.0f));   // MUFU chain
            // level 1-2 in registers
            int   seg = (pos >= r15) ? 16 : 0;
            float b2  = (pos >= r15) ? r23 : r7;
            seg += (pos >= b2) ? 8 : 0;
            // level 3-5 via LDS
            #pragma unroll
            for (int st = 4; st >= 1; st >>= 1) {
                int cand = seg + st;
                seg = (pos >= pbp[cand - 1]) ? cand : seg;
            }
            float2 si = segt[seg];
            rp[m] = fmaf(t, si.x, si.y);
        }
        op[k * 32 + lane] = r;
    }
}

extern "C" void kernel_launch(void* const* d_in, const int* in_sizes, int n_in,
                              void* d_out, int out_size)
{
    const float* logits = (const float*)d_in[0];  // (1,12,768,768)
    const float* W_in   = (const float*)d_in[1];  // (32,1)
    const float* b_in   = (const float*)d_in[2];  // (32,)
    const float* W_out  = (const float*)d_in[3];  // (12,32)
    const float* b_out  = (const float*)d_in[4];  // (12,)
    const float* c      = (const float*)d_in[5];
    const float* lmul   = (const float*)d_in[6];
    const float* initL  = (const float*)d_in[7];
    float* out = (float*)d_out;

    cope_fire_fused<<<(CPF_H * CPF_S) / CPF_RPB, 256>>>(
        logits, W_in, b_in, W_out, b_out, c, lmul, initL, out);
}